// round 9
// baseline (speedup 1.0000x reference)
#include <cuda_runtime.h>
#include <cuda_bf16.h>
#include <cstdint>
#include <cstddef>

#define DK 256        // feature dim
#define NC 32         // nodes per chunk (GEMM2 K)
#define ZS 74         // split-K CTAs per d-tile (x2 d-tiles = 148 CTAs)

// ---- smem layout: W resident + double-buffered nodes/yT; NO mask tile ----
#define W_STRIDE  528                      // 256 bf16 + 8 pad
#define ND_STRIDE 528
#define YT_STRIDE 80                       // 32 bf16 + 8 pad
#define OFF_WT 0
#define OFF_WG 67584                       // 128*528
#define OFF_ND 135168                      // 2 x (32*528 = 16896)
#define OFF_YT 168960                      // 2 x (128*80 = 10240)
#define SMEM_TOTAL 189440

static __device__ __forceinline__ uint32_t smem_u32(const void* p) {
    uint32_t a;
    asm("{ .reg .u64 t; cvta.to.shared.u64 t, %1; cvt.u32.u64 %0, t; }" : "=r"(a) : "l"(p));
    return a;
}

#define LDSM_X4(R, addr)                                                      \
    asm volatile("ldmatrix.sync.aligned.m8n8.x4.shared.b16 {%0,%1,%2,%3}, [%4];" \
                 : "=r"((R)[0]), "=r"((R)[1]), "=r"((R)[2]), "=r"((R)[3])     \
                 : "r"(addr))

#define MMA_BF16(C, A, b0, b1)                                                \
    asm volatile("mma.sync.aligned.m16n8k16.row.col.f32.bf16.bf16.f32 "       \
                 "{%0,%1,%2,%3},{%4,%5,%6,%7},{%8,%9},{%0,%1,%2,%3};"         \
                 : "+f"((C)[0]), "+f"((C)[1]), "+f"((C)[2]), "+f"((C)[3])     \
                 : "r"((A)[0]), "r"((A)[1]), "r"((A)[2]), "r"((A)[3]),        \
                   "r"(b0), "r"(b1))

// mask int {0,1} pair -> packed bf16x2 {1.0 or 0.0}: exact, 2 IMADs
static __device__ __forceinline__ uint32_t cvtm(int2 v) {
    return (uint32_t)v.x * 0x3F80u + (uint32_t)v.y * 0x3F800000u;
}

static __device__ __forceinline__ void store_bf4(char* p, float4 v) {
    __nv_bfloat162 lo = __floats2bfloat162_rn(v.x, v.y);
    __nv_bfloat162 hi = __floats2bfloat162_rn(v.z, v.w);
    uint2 u;
    u.x = *reinterpret_cast<uint32_t*>(&lo);
    u.y = *reinterpret_cast<uint32_t*>(&hi);
    *reinterpret_cast<uint2*>(p) = u;
}

static __device__ __forceinline__ float sigm(float x) { return 1.0f / (1.0f + __expf(-x)); }

// ---------------------------------------------------------------------------
// Software-pipelined fused kernel, ONE barrier per chunk:
//   iter it (chunk c):  STS nodes(c) | bar | GEMM2(it-1)+GEMM1(it) | yT STS
// Mask fragments loaded gmem->reg directly (no smem), one chunk ahead.
// ---------------------------------------------------------------------------
__global__ __launch_bounds__(512, 1)
void fused_agg(const float* __restrict__ nodes, const int* __restrict__ mask,
               const float* __restrict__ Wt, const float* __restrict__ bt,
               const float* __restrict__ Wg, const float* __restrict__ bg,
               float* __restrict__ out, int Nn)
{
    extern __shared__ char sm[];
    const uint32_t sb = smem_u32(sm);
    const int tid  = threadIdx.x;
    const int lane = tid & 31;
    const int wid  = tid >> 5;
    const int g    = lane >> 2;
    const int tg   = lane & 3;
    const int z    = blockIdx.x;
    const int d0   = blockIdx.y * 128;

    // GEMM1 warp roles: 8 m-warps (16 d rows) x 2 n-warps (16 n cols)
    const int wm = wid & 7;
    const int wn = wid >> 3;

    const float bt0 = bt[d0 + wm * 16 + g];
    const float bt1 = bt[d0 + wm * 16 + 8 + g];
    const float bg0 = bg[d0 + wm * 16 + g];
    const float bg1 = bg[d0 + wm * 16 + 8 + g];

    // GEMM2 (warp tile 16b x 128d): mask rows for this lane
    const int mrow0 = wid * 16 + g;
    const int mrow1 = mrow0 + 8;

    // Persistent GEMM2 accumulators
    float acc2[16][4];
    #pragma unroll
    for (int j = 0; j < 16; j++)
        #pragma unroll
        for (int q = 0; q < 4; q++) acc2[j][q] = 0.f;

    const int NCHK = Nn / NC;

    // ---- stage resident W (both matrices, f32 -> bf16) ----
    #pragma unroll
    for (int i = 0; i < 16; i++) {
        int f4  = tid + i * 512;
        int row = f4 >> 6;
        int col = (f4 & 63) * 4;
        store_bf4(sm + OFF_WT + row * W_STRIDE + col * 2,
                  *(const float4*)(Wt + (size_t)(d0 + row) * DK + col));
        store_bf4(sm + OFF_WG + row * W_STRIDE + col * 2,
                  *(const float4*)(Wg + (size_t)(d0 + row) * DK + col));
    }

    // ldmatrix lane addresses (buffer offset added per iter)
    const uint32_t aWt = sb + OFF_WT + (wm * 16 + (lane & 15)) * W_STRIDE + ((lane >> 4) << 4);
    const uint32_t aWg = aWt + (OFF_WG - OFF_WT);
    const uint32_t bNd = sb + OFF_ND
                       + (wn * 16 + (lane & 7) + ((lane >> 4) << 3)) * ND_STRIDE
                       + (((lane >> 3) & 1) << 4);
    const uint32_t bY  = sb + OFF_YT
                       + ((lane & 7) + ((lane >> 4) << 3)) * YT_STRIDE
                       + (((lane >> 3) & 1) << 4);

    // nodes register staging
    const int srow = tid >> 4;
    const int sc16 = tid & 15;
    float4 rN[4];
    {
        const float* src = nodes + (size_t)(z * NC + srow) * DK + sc16 * 4;
        #pragma unroll
        for (int i = 0; i < 4; i++) rN[i] = *(const float4*)(src + i * 64);
    }

    // mask fragments for current chunk (loaded gmem->reg, used NEXT iter's GEMM2)
    uint32_t am[8];
    {
        const int* p0 = mask + (size_t)mrow0 * Nn + z * NC + 2 * tg;
        const int* p1 = mask + (size_t)mrow1 * Nn + z * NC + 2 * tg;
        #pragma unroll
        for (int ks = 0; ks < 2; ks++) {
            am[ks * 4 + 0] = cvtm(*(const int2*)(p0 + ks * 16));
            am[ks * 4 + 1] = cvtm(*(const int2*)(p1 + ks * 16));
            am[ks * 4 + 2] = cvtm(*(const int2*)(p0 + ks * 16 + 8));
            am[ks * 4 + 3] = cvtm(*(const int2*)(p1 + ks * 16 + 8));
        }
    }

    int it = 0;
    for (int c = z; c < NCHK; c += ZS, ++it) {
        const uint32_t ndb = (uint32_t)(it & 1) * 16896u;
        const uint32_t ytb = (uint32_t)(it & 1) * 10240u;
        const uint32_t ytp = (uint32_t)((it ^ 1) & 1) * 10240u;   // previous yT buffer

        // ---- STS nodes(c) from prefetched regs ----
        {
            char* dst = sm + OFF_ND + ndb + srow * ND_STRIDE + sc16 * 8;
            #pragma unroll
            for (int i = 0; i < 4; i++) store_bf4(dst + i * 128, rN[i]);
        }
        __syncthreads();   // nodes(c) + yT(it-1) visible  [single barrier]

        // ---- prefetch nodes(c+ZS) ----
        if (c + ZS < NCHK) {
            const float* src = nodes + (size_t)((c + ZS) * NC + srow) * DK + sc16 * 4;
            #pragma unroll
            for (int i = 0; i < 4; i++) rN[i] = *(const float4*)(src + i * 64);
        }

        // ---- GEMM2(it-1): acc2 += mask(prev) @ yT(prev) ----
        if (it > 0) {
            #pragma unroll
            for (int ks = 0; ks < 2; ks++) {
                const uint32_t* A = am + ks * 4;
                #pragma unroll
                for (int nf = 0; nf < 8; nf++) {
                    uint32_t Y[4];
                    LDSM_X4(Y, bY + ytp + nf * 16 * YT_STRIDE + ks * 32);
                    MMA_BF16(acc2[2 * nf],     A, Y[0], Y[1]);
                    MMA_BF16(acc2[2 * nf + 1], A, Y[2], Y[3]);
                }
            }
        }

        // ---- reload mask fragments for chunk c (consumed next iter) ----
        {
            const int* p0 = mask + (size_t)mrow0 * Nn + c * NC + 2 * tg;
            const int* p1 = mask + (size_t)mrow1 * Nn + c * NC + 2 * tg;
            #pragma unroll
            for (int ks = 0; ks < 2; ks++) {
                am[ks * 4 + 0] = cvtm(*(const int2*)(p0 + ks * 16));
                am[ks * 4 + 1] = cvtm(*(const int2*)(p1 + ks * 16));
                am[ks * 4 + 2] = cvtm(*(const int2*)(p0 + ks * 16 + 8));
                am[ks * 4 + 3] = cvtm(*(const int2*)(p1 + ks * 16 + 8));
            }
        }

        // ---- GEMM1(it): yT = W @ nodes(c)^T  (M=128, N=32, K=256) ----
        float aT0[4] = {0,0,0,0}, aT1[4] = {0,0,0,0};
        float aG0[4] = {0,0,0,0}, aG1[4] = {0,0,0,0};
        #pragma unroll
        for (int ks = 0; ks < 16; ks++) {
            uint32_t At[4], Ag[4], Bn[4];
            LDSM_X4(At, aWt + ks * 32);
            LDSM_X4(Ag, aWg + ks * 32);
            LDSM_X4(Bn, bNd + ndb + ks * 32);
            MMA_BF16(aT0, At, Bn[0], Bn[1]);
            MMA_BF16(aT1, At, Bn[2], Bn[3]);
            MMA_BF16(aG0, Ag, Bn[0], Bn[1]);
            MMA_BF16(aG1, Ag, Bn[2], Bn[3]);
        }

        // ---- epilogue: y = (t+bt)*sigmoid(g+bg) -> yT(it) smem bf16 ----
        {
            char* r0 = sm + OFF_YT + ytb + (wm * 16 + g) * YT_STRIDE + (wn * 16 + 2 * tg) * 2;
            char* r1 = r0 + 8 * YT_STRIDE;
            __nv_bfloat162 h;
            h = __floats2bfloat162_rn((aT0[0] + bt0) * sigm(aG0[0] + bg0),
                                      (aT0[1] + bt0) * sigm(aG0[1] + bg0));
            *(uint32_t*)r0 = *reinterpret_cast<uint32_t*>(&h);
            h = __floats2bfloat162_rn((aT0[2] + bt1) * sigm(aG0[2] + bg1),
                                      (aT0[3] + bt1) * sigm(aG0[3] + bg1));
            *(uint32_t*)r1 = *reinterpret_cast<uint32_t*>(&h);
            h = __floats2bfloat162_rn((aT1[0] + bt0) * sigm(aG1[0] + bg0),
                                      (aT1[1] + bt0) * sigm(aG1[1] + bg0));
            *(uint32_t*)(r0 + 16) = *reinterpret_cast<uint32_t*>(&h);
            h = __floats2bfloat162_rn((aT1[2] + bt1) * sigm(aG1[2] + bg1),
                                      (aT1[3] + bt1) * sigm(aG1[3] + bg1));
            *(uint32_t*)(r1 + 16) = *reinterpret_cast<uint32_t*>(&h);
        }
    }

    // ---- tail: GEMM2 for the last produced yT ----
    if (it > 0) {
        __syncthreads();
        const uint32_t ytp = (uint32_t)((it ^ 1) & 1) * 10240u;
        #pragma unroll
        for (int ks = 0; ks < 2; ks++) {
            const uint32_t* A = am + ks * 4;
            #pragma unroll
            for (int nf = 0; nf < 8; nf++) {
                uint32_t Y[4];
                LDSM_X4(Y, bY + ytp + nf * 16 * YT_STRIDE + ks * 32);
                MMA_BF16(acc2[2 * nf],     A, Y[0], Y[1]);
                MMA_BF16(acc2[2 * nf + 1], A, Y[2], Y[3]);
            }
        }
    }

    // ---- drain: atomic-accumulate split-K partials ----
    {
        const int r = wid * 16 + g;
        #pragma unroll
        for (int j = 0; j < 16; j++) {
            const int cb = d0 + j * 8 + 2 * tg;
            atomicAdd(out + (size_t)r * DK + cb,           acc2[j][0]);
            atomicAdd(out + (size_t)r * DK + cb + 1,       acc2[j][1]);
            atomicAdd(out + (size_t)(r + 8) * DK + cb,     acc2[j][2]);
            atomicAdd(out + (size_t)(r + 8) * DK + cb + 1, acc2[j][3]);
        }
    }
}

__global__ void kzero(float* __restrict__ o, int n) {
    const int i = blockIdx.x * 256 + threadIdx.x;
    if (i < n) o[i] = 0.f;
}

extern "C" void kernel_launch(void* const* d_in, const int* in_sizes, int n_in,
                              void* d_out, int out_size)
{
    const float* nodes = (const float*)d_in[0];
    const int*   mask  = (const int*)  d_in[1];
    const float* Wt    = (const float*)d_in[2];
    const float* bt    = (const float*)d_in[3];
    const float* Wg    = (const float*)d_in[4];
    const float* bg    = (const float*)d_in[5];
    float* out = (float*)d_out;

    const int Nn = in_sizes[0] / DK;   // 200000

    cudaFuncSetAttribute(fused_agg, cudaFuncAttributeMaxDynamicSharedMemorySize, SMEM_TOTAL);

    kzero<<<(out_size + 255) / 256, 256>>>(out, out_size);
    fused_agg<<<dim3(ZS, 2), 512, SMEM_TOTAL>>>(nodes, mask, Wt, bt, Wg, bg, out, Nn);
}